// round 16
// baseline (speedup 1.0000x reference)
#include <cuda_runtime.h>
#include <math.h>
#include <stdint.h>

#define NTOK 8192
#define DIM  1024
#define NEXP 8
#define BM   128
#define BN   128
#define BK   16
#define NTHREADS 512
#define PADROWS (NTOK + NEXP*128)     // 9216 worst-case padded rows
#define PADTILES (PADROWS / 128)      // 72
#define SMEM_BYTES (2 * 4 * BK * 136 * 4)   // As[4]+Bs[4] = 69632

// ---------------- device scratch (alloc-free rule) ----------------
// Reference ONLY from device code (host-side use gets the ATS host-shadow
// address — root cause of the R7-R10 anomalies).
__device__ int   g_eid[NTOK];
__device__ float g_w[NTOK];
__device__ int   g_counts[NEXP];
__device__ int   g_offs[NEXP];
__device__ int   g_padcnt[NEXP];
__device__ int   g_pperm[PADROWS];
// k-major blocked hidden activations: [tile][k][128 rows]
__device__ __align__(256) float g_h  [(size_t)PADTILES * DIM * 128];
// RNA-rounded weights (device-resident)
__device__ __align__(256) float g_w1r[(size_t)NEXP * DIM * DIM];
__device__ __align__(256) float g_w2r[(size_t)NEXP * DIM * DIM];

__device__ __forceinline__ float to_tf32(float v) {
    float r; asm("cvt.rna.tf32.f32 %0, %1;" : "=f"(r) : "f"(v)); return r;
}
__device__ __forceinline__ uint32_t smem_u32(const void* p) {
    uint32_t a;
    asm("{ .reg .u64 t; cvta.to.shared.u64 t, %1; cvt.u32.u64 %0, t; }" : "=r"(a) : "l"(p));
    return a;
}
__device__ __forceinline__ void cp16(uint32_t s, const void* g) {
    asm volatile("cp.async.cg.shared.global [%0], [%1], 16;" :: "r"(s), "l"(g));
}

// ---------------- fused prep: init counts + fill perm + round both W ----------------
__global__ void prep_kernel(const float* __restrict__ W1, const float* __restrict__ W2) {
    const int b = blockIdx.x, t = threadIdx.x;
    if (b == 0 && t < NEXP) g_counts[t] = 0;
    int pidx = b * 256 + t;
    if (pidx < PADROWS) g_pperm[pidx] = -1;

    size_t i = (size_t)b * 256 + t;                      // 0 .. 4M-1
    const size_t HALF = (size_t)NEXP * DIM * DIM / 4;    // 2M float4 per matrix
    if (i < HALF) {
        float4 v = ((const float4*)W1)[i];
        v.x = to_tf32(v.x); v.y = to_tf32(v.y); v.z = to_tf32(v.z); v.w = to_tf32(v.w);
        ((float4*)g_w1r)[i] = v;
    } else {
        size_t j = i - HALF;
        float4 v = ((const float4*)W2)[j];
        v.x = to_tf32(v.x); v.y = to_tf32(v.y); v.z = to_tf32(v.z); v.w = to_tf32(v.w);
        ((float4*)g_w2r)[j] = v;
    }
}

// ---------------- gating ----------------
__global__ void gate_kernel(const float* __restrict__ x,
                            const float* __restrict__ Wg,
                            const float* __restrict__ bg) {
    int warp = (blockIdx.x * blockDim.x + threadIdx.x) >> 5;
    int lane = threadIdx.x & 31;
    if (warp >= NTOK) return;
    const float* xr = x + (size_t)warp * DIM;
    float acc[NEXP];
#pragma unroll
    for (int e = 0; e < NEXP; e++) acc[e] = 0.f;
    for (int d = lane; d < DIM; d += 32) {
        float xv = xr[d];
        const float* wr = Wg + d * NEXP;
#pragma unroll
        for (int e = 0; e < NEXP; e++) acc[e] = fmaf(xv, wr[e], acc[e]);
    }
#pragma unroll
    for (int e = 0; e < NEXP; e++) {
#pragma unroll
        for (int o = 16; o > 0; o >>= 1)
            acc[e] += __shfl_xor_sync(0xffffffffu, acc[e], o);
    }
    if (lane == 0) {
        float l[NEXP];
        float best = -1e30f; int bi = 0;
#pragma unroll
        for (int e = 0; e < NEXP; e++) {
            l[e] = acc[e] + bg[e];
            if (l[e] > best) { best = l[e]; bi = e; }   // first-max, matches jnp.argmax
        }
        float s = 0.f;
#pragma unroll
        for (int e = 0; e < NEXP; e++) s += expf(l[e] - best);
        g_eid[warp] = bi;
        g_w[warp]   = 1.0f / s;
        atomicAdd(&g_counts[bi], 1);
    }
}

// ---------------- fused scan + scatter (single block) ----------------
__global__ void group_kernel() {
    __shared__ int sfill[NEXP];
    const int t = threadIdx.x;   // 1024 threads
    if (t == 0) {
        int o = 0;
        for (int e = 0; e < NEXP; e++) {
            int pc = ((g_counts[e] + BM - 1) / BM) * BM;
            g_padcnt[e] = pc;
            g_offs[e]   = o;
            sfill[e]    = o;
            o += pc;
        }
    }
    __syncthreads();
    for (int tok = t; tok < NTOK; tok += 1024) {
        int e = g_eid[tok];
        int pos = atomicAdd(&sfill[e], 1);
        g_pperm[pos] = tok;
    }
}

// ---------------- tf32 mma.sync grouped GEMM, 512 threads, warp tile 32x32 ----------------
// 16 warps (4m x 4n) -> acc 32 regs/thread -> 2 CTAs/SM = 32 warps/SM (occ ~44%).
// cp.async 4-stage ring for B (and stage-2 A); stage-1 A via conflict-free
// register gather+transpose one stage ahead. One __syncthreads per k-iter.
#define MMA_TF32(d, a, b)                                                        \
    asm volatile(                                                                \
        "mma.sync.aligned.m16n8k8.row.col.f32.tf32.tf32.f32 "                    \
        "{%0,%1,%2,%3}, {%4,%5,%6,%7}, {%8,%9}, {%0,%1,%2,%3};"                  \
        : "+f"((d)[0]), "+f"((d)[1]), "+f"((d)[2]), "+f"((d)[3])                 \
        : "r"((a)[0]), "r"((a)[1]), "r"((a)[2]), "r"((a)[3]),                    \
          "r"((b)[0]), "r"((b)[1]))

template <int STAGE>
__global__ void __launch_bounds__(NTHREADS, 2)
gemm_mma(const float* __restrict__ X, const float* __restrict__ Bias,
         float* __restrict__ out) {
    extern __shared__ float dynsm[];
    float* Asm = dynsm;                    // [4][BK][136]
    float* Bsm = dynsm + 4 * BK * 136;     // [4][BK][136]
#define AS(bf,k,m) Asm[((bf) * BK + (k)) * 136 + (m)]
#define BS(bf,k,n) Bsm[((bf) * BK + (k)) * 136 + (n)]

    const int e  = blockIdx.z;
    const int m0 = blockIdx.y * BM;
    if (m0 >= g_padcnt[e]) return;
    const int n0   = blockIdx.x * BN;
    const int off  = g_offs[e];
    const int tile = (off + m0) >> 7;

    const float* Abase = g_h + (size_t)tile * DIM * 128;                      // STAGE 2
    const float* Bbase = (STAGE == 1 ? g_w1r : g_w2r) + (size_t)e * DIM * DIM;

    const int tid  = threadIdx.x;        // 0..511
    const int lane = tid & 31;
    const int wid  = tid >> 5;           // 0..15
    const int wmb  = (wid >> 2) * 32;    // 0,32,64,96
    const int wnb  = (wid & 3) * 32;     // 0,32,64,96
    const int g    = lane >> 2;
    const int t4   = lane & 3;

    // cp.async staging coords: one 16B chunk per thread per operand
    const int krA = tid >> 5;              // 0..15
    const int chA = (tid & 31) * 4;        // 0..124
    const uint32_t sB0 = smem_u32(Bsm) + (uint32_t)(krA * 136 + chA) * 4;
    const uint32_t sA0 = smem_u32(Asm) + (uint32_t)(krA * 136 + chA) * 4;
    const uint32_t bufB = (uint32_t)(BK * 136) * 4;    // bytes per buffer

    // stage-1 A gather: row arow, 4 consecutive k at koff; warp lanes span 32
    // consecutive rows -> STS banks = arow%32 -> conflict-free
    const int arow = tid & 127;            // 0..127
    const int koff = (tid >> 7) * 4;       // 0,4,8,12
    const float* xrow = nullptr;
    if (STAGE == 1) {
        int tokA = g_pperm[off + m0 + arow];
        if (tokA >= 0) xrow = X + (size_t)tokA * DIM;
    }
    float4 qa;

    auto issueCp = [&](int it, int bf) {   // B always; A too in stage 2
        const int k0 = it * BK;
        cp16(sB0 + bf * bufB, Bbase + (size_t)(k0 + krA) * DIM + n0 + chA);
        if (STAGE == 2)
            cp16(sA0 + bf * bufB, Abase + (size_t)(k0 + krA) * 128 + chA);
    };
    auto loadA1 = [&](int k0) {
        qa = xrow ? *(const float4*)(xrow + k0 + koff)
                  : make_float4(0.f, 0.f, 0.f, 0.f);
    };
    auto storeA1 = [&](int bf) {           // transpose + tf32-round
        AS(bf, koff + 0, arow) = to_tf32(qa.x);
        AS(bf, koff + 1, arow) = to_tf32(qa.y);
        AS(bf, koff + 2, arow) = to_tf32(qa.z);
        AS(bf, koff + 3, arow) = to_tf32(qa.w);
    };

    float acc[2][4][4];
#pragma unroll
    for (int mi = 0; mi < 2; mi++)
#pragma unroll
        for (int nj = 0; nj < 4; nj++)
#pragma unroll
            for (int r = 0; r < 4; r++) acc[mi][nj][r] = 0.f;

    const int NIT = DIM / BK;   // 64

    // prologue: issue cp stages 0..2; stage-1 A slab 0 via registers
#pragma unroll
    for (int s = 0; s < 3; s++) {
        issueCp(s, s);
        asm volatile("cp.async.commit_group;");
    }
    if (STAGE == 1) { loadA1(0); storeA1(0); }

    for (int it = 0; it < NIT; ++it) {
        const int bf = it & 3;

        asm volatile("cp.async.wait_group 2;");
        __syncthreads();   // group-it data + last iter's A stores visible

        if (STAGE == 1 && it + 1 < NIT) loadA1((it + 1) * BK);

        if (it + 3 < NIT) issueCp(it + 3, (it + 3) & 3);
        asm volatile("cp.async.commit_group;");   // empty tail groups keep count uniform

        // compute buffer bf (2 x K=8)
#pragma unroll
        for (int kk = 0; kk < 2; kk++) {
            const int kb = kk * 8;
            uint32_t a[2][4], b[4][2];
#pragma unroll
            for (int mi = 0; mi < 2; mi++) {
                int m = wmb + mi * 16;
                a[mi][0] = __float_as_uint(AS(bf, kb + t4,     m + g    ));
                a[mi][1] = __float_as_uint(AS(bf, kb + t4,     m + g + 8));
                a[mi][2] = __float_as_uint(AS(bf, kb + t4 + 4, m + g    ));
                a[mi][3] = __float_as_uint(AS(bf, kb + t4 + 4, m + g + 8));
            }
#pragma unroll
            for (int nj = 0; nj < 4; nj++) {
                int n = wnb + nj * 8;
                b[nj][0] = __float_as_uint(BS(bf, kb + t4,     n + g));
                b[nj][1] = __float_as_uint(BS(bf, kb + t4 + 4, n + g));
            }
#pragma unroll
            for (int mi = 0; mi < 2; mi++)
#pragma unroll
                for (int nj = 0; nj < 4; nj++)
                    MMA_TF32(acc[mi][nj], a[mi], b[nj]);
        }

        if (STAGE == 1 && it + 1 < NIT) storeA1((it + 1) & 3);
    }

    // ---- epilogue ----
    if (STAGE == 1) {
        float* Hbase = g_h + (size_t)tile * DIM * 128;
#pragma unroll
        for (int mi = 0; mi < 2; mi++) {
            int mA = wmb + mi * 16 + g;
            int mB = mA + 8;
#pragma unroll
            for (int nj = 0; nj < 4; nj++) {
                int n = n0 + wnb + nj * 8 + t4 * 2;
                float bi0 = Bias[e * DIM + n];
                float bi1 = Bias[e * DIM + n + 1];
                float v0 = acc[mi][nj][0] + bi0;
                float v1 = acc[mi][nj][1] + bi1;
                float v2 = acc[mi][nj][2] + bi0;
                float v3 = acc[mi][nj][3] + bi1;
                Hbase[(size_t)n * 128 + mA]       = to_tf32(0.5f * v0 * (1.0f + erff(v0 * 0.70710678118654752f)));
                Hbase[(size_t)(n + 1) * 128 + mA] = to_tf32(0.5f * v1 * (1.0f + erff(v1 * 0.70710678118654752f)));
                Hbase[(size_t)n * 128 + mB]       = to_tf32(0.5f * v2 * (1.0f + erff(v2 * 0.70710678118654752f)));
                Hbase[(size_t)(n + 1) * 128 + mB] = to_tf32(0.5f * v3 * (1.0f + erff(v3 * 0.70710678118654752f)));
            }
        }
    } else {
        const int prow = off + m0;
#pragma unroll
        for (int mi = 0; mi < 2; mi++) {
            int mA = wmb + mi * 16 + g;
            int mB = mA + 8;
            int tokA = g_pperm[prow + mA];
            int tokB = g_pperm[prow + mB];
            float wA = (tokA >= 0) ? g_w[tokA] : 0.f;
            float wB = (tokB >= 0) ? g_w[tokB] : 0.f;
#pragma unroll
            for (int nj = 0; nj < 4; nj++) {
                int n = n0 + wnb + nj * 8 + t4 * 2;
                float bi0 = Bias[e * DIM + n];
                float bi1 = Bias[e * DIM + n + 1];
                if (tokA >= 0) {
                    out[(size_t)tokA * DIM + n]     = wA * (acc[mi][nj][0] + bi0);
                    out[(size_t)tokA * DIM + n + 1] = wA * (acc[mi][nj][1] + bi1);
                }
                if (tokB >= 0) {
                    out[(size_t)tokB * DIM + n]     = wB * (acc[mi][nj][2] + bi0);
                    out[(size_t)tokB * DIM + n + 1] = wB * (acc[mi][nj][3] + bi1);
                }
            }
        }
    }
#undef AS
#undef BS
}

// ---------------------------------------------------------------------------
extern "C" void kernel_launch(void* const* d_in, const int* in_sizes, int n_in,
                              void* d_out, int out_size) {
    const float* x  = (const float*)d_in[0];
    const float* Wg = (const float*)d_in[1];
    const float* bg = (const float*)d_in[2];
    const float* W1 = (const float*)d_in[3];
    const float* b1 = (const float*)d_in[4];
    const float* W2 = (const float*)d_in[5];
    const float* b2 = (const float*)d_in[6];
    float* out = (float*)d_out;

    cudaFuncSetAttribute(gemm_mma<1>, cudaFuncAttributeMaxDynamicSharedMemorySize, SMEM_BYTES);
    cudaFuncSetAttribute(gemm_mma<2>, cudaFuncAttributeMaxDynamicSharedMemorySize, SMEM_BYTES);

    prep_kernel<<<16384, 256>>>(W1, W2);                       // 1
    gate_kernel<<<(NTOK * 32 + 255) / 256, 256>>>(x, Wg, bg);  // 2
    group_kernel<<<1, 1024>>>();                               // 3

    dim3 grid(DIM / BN, PADTILES, NEXP);
    gemm_mma<1><<<grid, NTHREADS, SMEM_BYTES>>>(x, b1, nullptr);    // 4 <- profiled
    gemm_mma<2><<<grid, NTHREADS, SMEM_BYTES>>>(nullptr, b2, out);  // 5
}